// round 2
// baseline (speedup 1.0000x reference)
#include <cuda_runtime.h>
#include <math.h>

#define SEQ    4096
#define DMODEL 1024
#define HEADS  8
#define ZIPD   256
#define DH     32      // ZIP / HEADS
#define DV     128     // DMODEL / HEADS

// ---------------- scratch (no allocation allowed) ----------------
__device__ __align__(16) float g_Q[SEQ * ZIPD];     // 4 MB
__device__ __align__(16) float g_K[SEQ * ZIPD];     // 4 MB
__device__ __align__(16) float g_T[SEQ * ZIPD];     // 4 MB
__device__ __align__(16) float g_V[SEQ * DMODEL];   // 16 MB

// ---------------- GEMM: C[M,N] = A[M,K] @ W[N,K]^T + bias[N] ----------------
// BM=BN=128, BK=16, 256 threads, 8x8 micro-tile split into 4+4 halves.
#define BKG 16
#define GPAD 132   // 128 + 4 padding (reduces transpose-store conflicts)

__device__ __forceinline__ void gemm_body(const float* __restrict__ A,
                                          const float* __restrict__ W,
                                          const float* __restrict__ bias,
                                          float* __restrict__ C,
                                          int N, int K)
{
    __shared__ float As[BKG][GPAD];
    __shared__ float Ws[BKG][GPAD];

    const int tid = threadIdx.x;
    const int tx  = tid & 15;
    const int ty  = tid >> 4;
    const int m0  = blockIdx.y * 128;
    const int n0  = blockIdx.x * 128;
    const int lc  = tid & 3;    // float4 column within 16-wide k-slice
    const int lr  = tid >> 2;   // 0..63 ; rows lr and lr+64

    float acc[8][8];
#pragma unroll
    for (int i = 0; i < 8; i++)
#pragma unroll
        for (int j = 0; j < 8; j++) acc[i][j] = 0.f;

    for (int k0 = 0; k0 < K; k0 += BKG) {
        float4 a0 = *(const float4*)(A + (size_t)(m0 + lr)      * K + k0 + lc * 4);
        float4 a1 = *(const float4*)(A + (size_t)(m0 + lr + 64) * K + k0 + lc * 4);
        float4 w0 = *(const float4*)(W + (size_t)(n0 + lr)      * K + k0 + lc * 4);
        float4 w1 = *(const float4*)(W + (size_t)(n0 + lr + 64) * K + k0 + lc * 4);

        __syncthreads();   // previous iteration's compute reads are done
        As[lc * 4 + 0][lr] = a0.x;  As[lc * 4 + 1][lr] = a0.y;
        As[lc * 4 + 2][lr] = a0.z;  As[lc * 4 + 3][lr] = a0.w;
        As[lc * 4 + 0][lr + 64] = a1.x;  As[lc * 4 + 1][lr + 64] = a1.y;
        As[lc * 4 + 2][lr + 64] = a1.z;  As[lc * 4 + 3][lr + 64] = a1.w;
        Ws[lc * 4 + 0][lr] = w0.x;  Ws[lc * 4 + 1][lr] = w0.y;
        Ws[lc * 4 + 2][lr] = w0.z;  Ws[lc * 4 + 3][lr] = w0.w;
        Ws[lc * 4 + 0][lr + 64] = w1.x;  Ws[lc * 4 + 1][lr + 64] = w1.y;
        Ws[lc * 4 + 2][lr + 64] = w1.z;  Ws[lc * 4 + 3][lr + 64] = w1.w;
        __syncthreads();

#pragma unroll
        for (int kk = 0; kk < BKG; kk++) {
            float a[8], b[8];
            float4 t;
            t = *(const float4*)&As[kk][ty * 4];      a[0]=t.x; a[1]=t.y; a[2]=t.z; a[3]=t.w;
            t = *(const float4*)&As[kk][64 + ty * 4]; a[4]=t.x; a[5]=t.y; a[6]=t.z; a[7]=t.w;
            t = *(const float4*)&Ws[kk][tx * 4];      b[0]=t.x; b[1]=t.y; b[2]=t.z; b[3]=t.w;
            t = *(const float4*)&Ws[kk][64 + tx * 4]; b[4]=t.x; b[5]=t.y; b[6]=t.z; b[7]=t.w;
#pragma unroll
            for (int i = 0; i < 8; i++)
#pragma unroll
                for (int j = 0; j < 8; j++)
                    acc[i][j] = fmaf(a[i], b[j], acc[i][j]);
        }
    }

#pragma unroll
    for (int ih = 0; ih < 2; ih++) {
#pragma unroll
        for (int i = 0; i < 4; i++) {
            int row = m0 + ih * 64 + ty * 4 + i;
#pragma unroll
            for (int jh = 0; jh < 2; jh++) {
                int col = n0 + jh * 64 + tx * 4;
                float4 o;
                o.x = acc[ih * 4 + i][jh * 4 + 0] + bias[col + 0];
                o.y = acc[ih * 4 + i][jh * 4 + 1] + bias[col + 1];
                o.z = acc[ih * 4 + i][jh * 4 + 2] + bias[col + 2];
                o.w = acc[ih * 4 + i][jh * 4 + 3] + bias[col + 3];
                *(float4*)(C + (size_t)row * N + col) = o;
            }
        }
    }
}

// Fused projection kernel: z=0 -> Q, z=1 -> K, z=2 -> V right factor
__global__ void __launch_bounds__(256, 2)
proj_kernel(const float* __restrict__ q, const float* __restrict__ k,
            const float* __restrict__ v,
            const float* __restrict__ wq, const float* __restrict__ bq,
            const float* __restrict__ wk, const float* __restrict__ bk,
            const float* __restrict__ wvr, const float* __restrict__ bvr)
{
    const float *A, *W, *B;
    float* C;
    if (blockIdx.z == 0)      { A = q; W = wq;  B = bq;  C = g_Q; }
    else if (blockIdx.z == 1) { A = k; W = wk;  B = bk;  C = g_K; }
    else                      { A = v; W = wvr; B = bvr; C = g_T; }
    gemm_body(A, W, B, C, ZIPD, DMODEL);
}

// value = g_T @ w_v_l^T + b_v_l   ([4096,256] x [1024,256]^T)
__global__ void __launch_bounds__(256, 2)
vl_kernel(const float* __restrict__ wvl, const float* __restrict__ bvl)
{
    gemm_body(g_T, wvl, bvl, g_V, DMODEL, ZIPD);
}

// ---------------- Flash attention ----------------
// Block = 64 queries x one head, 256 threads (16x16).
// Score micro-tile: rows 4*ty+i (i<4), key cols 4*tx+j (j<4).
// Accumulator: rows 4*ty+i, d cols 2*tx + 32*j2 + u (j2<4, u<2).
#define BQ 64
#define BKT 64

__global__ void __launch_bounds__(256, 2)
attn_kernel(float* __restrict__ O)
{
    extern __shared__ float sm[];
    float* Qs = sm;                    // [DH][64]  k-major
    float* Ks = sm + DH * 64;          // [DH][64]  k-major
    float* Vs = sm + 2 * DH * 64;      // [64][DV]  row-major
    float* Ps = Vs + 64 * DV;          // [64][64]

    const int tid = threadIdx.x;
    const int tx  = tid & 15;
    const int ty  = tid >> 4;
    const int h   = blockIdx.y;
    const int q0  = blockIdx.x * BQ;

    // ---- load Q tile transposed: Qs[d][q] ----
    {
        const int c4 = tid & 7;    // which float4 of the 32-dim
        const int r  = tid >> 3;   // 0..31
#pragma unroll
        for (int rr = 0; rr < 2; rr++) {
            int row = r + rr * 32;
            float4 val = *(const float4*)(g_Q + (size_t)(q0 + row) * ZIPD + h * DH + c4 * 4);
            Qs[(c4 * 4 + 0) * 64 + row] = val.x;
            Qs[(c4 * 4 + 1) * 64 + row] = val.y;
            Qs[(c4 * 4 + 2) * 64 + row] = val.z;
            Qs[(c4 * 4 + 3) * 64 + row] = val.w;
        }
    }

    float m_i[4], l_i[4];
    float acc[4][8];
#pragma unroll
    for (int i = 0; i < 4; i++) {
        m_i[i] = -1e30f;
        l_i[i] = 0.f;
#pragma unroll
        for (int j = 0; j < 8; j++) acc[i][j] = 0.f;
    }

    for (int kt = 0; kt < SEQ / BKT; kt++) {
        const int k0 = kt * BKT;
        __syncthreads();  // previous tile's Ks/Vs/Ps reads finished (also covers Q load)

        // ---- load K tile transposed: Ks[d][k] ----
        {
            const int c4 = tid & 7;
            const int r  = tid >> 3;
#pragma unroll
            for (int rr = 0; rr < 2; rr++) {
                int row = r + rr * 32;
                float4 val = *(const float4*)(g_K + (size_t)(k0 + row) * ZIPD + h * DH + c4 * 4);
                Ks[(c4 * 4 + 0) * 64 + row] = val.x;
                Ks[(c4 * 4 + 1) * 64 + row] = val.y;
                Ks[(c4 * 4 + 2) * 64 + row] = val.z;
                Ks[(c4 * 4 + 3) * 64 + row] = val.w;
            }
        }
        // ---- load V tile: Vs[k][d] ----
        {
#pragma unroll
            for (int it = 0; it < 8; it++) {
                int idx = it * 256 + tid;
                int r = idx >> 5;
                int c = idx & 31;
                *(float4*)(Vs + r * DV + c * 4) =
                    *(const float4*)(g_V + (size_t)(k0 + r) * DMODEL + h * DV + c * 4);
            }
        }
        __syncthreads();

        // ---- scores: sc[i][j] = Q[4ty+i] . K[4tx+j] ----
        float sc[4][4];
#pragma unroll
        for (int i = 0; i < 4; i++)
#pragma unroll
            for (int j = 0; j < 4; j++) sc[i][j] = 0.f;

#pragma unroll
        for (int kk = 0; kk < DH; kk++) {
            float4 qa = *(const float4*)&Qs[kk * 64 + ty * 4];
            float4 kb = *(const float4*)&Ks[kk * 64 + tx * 4];
            float a[4] = {qa.x, qa.y, qa.z, qa.w};
            float b[4] = {kb.x, kb.y, kb.z, kb.w};
#pragma unroll
            for (int i = 0; i < 4; i++)
#pragma unroll
                for (int j = 0; j < 4; j++)
                    sc[i][j] = fmaf(a[i], b[j], sc[i][j]);
        }

        // ---- online softmax (row stats fully in registers; 16 lanes/row agree) ----
#pragma unroll
        for (int i = 0; i < 4; i++) {
            float mx = fmaxf(fmaxf(sc[i][0], sc[i][1]), fmaxf(sc[i][2], sc[i][3]));
#pragma unroll
            for (int o = 8; o > 0; o >>= 1)
                mx = fmaxf(mx, __shfl_xor_sync(0xffffffffu, mx, o, 16));
            float m_new = fmaxf(m_i[i], mx);
            float scale = __expf(m_i[i] - m_new);

            float p0 = __expf(sc[i][0] - m_new);
            float p1 = __expf(sc[i][1] - m_new);
            float p2 = __expf(sc[i][2] - m_new);
            float p3 = __expf(sc[i][3] - m_new);
            float psum = (p0 + p1) + (p2 + p3);
#pragma unroll
            for (int o = 8; o > 0; o >>= 1)
                psum += __shfl_xor_sync(0xffffffffu, psum, o, 16);

            l_i[i] = l_i[i] * scale + psum;
            m_i[i] = m_new;
#pragma unroll
            for (int j = 0; j < 8; j++) acc[i][j] *= scale;

            *(float4*)&Ps[(ty * 4 + i) * 64 + tx * 4] = make_float4(p0, p1, p2, p3);
        }
        __syncthreads();

        // ---- PV: acc[i][2*j2+u] += P[row][k] * V[k][32*j2 + 2*tx + u] ----
#pragma unroll 4
        for (int k = 0; k < BKT; k++) {
            float pr[4];
#pragma unroll
            for (int i = 0; i < 4; i++) pr[i] = Ps[(ty * 4 + i) * 64 + k];
#pragma unroll
            for (int j2 = 0; j2 < 4; j2++) {
                float2 vv = *(const float2*)&Vs[k * DV + j2 * 32 + tx * 2];
#pragma unroll
                for (int i = 0; i < 4; i++) {
                    acc[i][j2 * 2 + 0] = fmaf(pr[i], vv.x, acc[i][j2 * 2 + 0]);
                    acc[i][j2 * 2 + 1] = fmaf(pr[i], vv.y, acc[i][j2 * 2 + 1]);
                }
            }
        }
    }

    // ---- epilogue ----
#pragma unroll
    for (int i = 0; i < 4; i++) {
        float inv = 1.f / l_i[i];
        int row = q0 + ty * 4 + i;
#pragma unroll
        for (int j2 = 0; j2 < 4; j2++) {
            float2 o;
            o.x = acc[i][j2 * 2 + 0] * inv;
            o.y = acc[i][j2 * 2 + 1] * inv;
            *(float2*)(O + (size_t)row * DMODEL + h * DV + j2 * 32 + tx * 2) = o;
        }
    }
}

// ---------------- launch ----------------
extern "C" void kernel_launch(void* const* d_in, const int* in_sizes, int n_in,
                              void* d_out, int out_size)
{
    const float* q   = (const float*)d_in[0];
    const float* k   = (const float*)d_in[1];
    const float* v   = (const float*)d_in[2];
    const float* wq  = (const float*)d_in[3];
    const float* bq  = (const float*)d_in[4];
    const float* wk  = (const float*)d_in[5];
    const float* bk  = (const float*)d_in[6];
    const float* wvr = (const float*)d_in[7];
    const float* bvr = (const float*)d_in[8];
    const float* wvl = (const float*)d_in[9];
    const float* bvl = (const float*)d_in[10];
    float* out = (float*)d_out;

    // q/k/v_r projections fused into one launch (grid.z picks the triple)
    dim3 pgrid(ZIPD / 128, SEQ / 128, 3);
    proj_kernel<<<pgrid, 256>>>(q, k, v, wq, bq, wk, bk, wvr, bvr);

    dim3 vgrid(DMODEL / 128, SEQ / 128, 1);
    vl_kernel<<<vgrid, 256>>>(wvl, bvl);

    const int ATTN_SMEM = (2 * DH * 64 + 64 * DV + 64 * 64) * (int)sizeof(float); // 64 KB
    cudaFuncSetAttribute(attn_kernel, cudaFuncAttributeMaxDynamicSharedMemorySize, ATTN_SMEM);
    attn_kernel<<<dim3(SEQ / BQ, HEADS), 256, ATTN_SMEM>>>(out);
}

// round 3
// speedup vs baseline: 2.3871x; 2.3871x over previous
#include <cuda_runtime.h>
#include <cuda_fp16.h>
#include <math.h>

#define SEQ    4096
#define DMODEL 1024
#define HEADS  8
#define ZIPD   256
#define DH     32      // ZIP / HEADS
#define DV     128     // DMODEL / HEADS

// ---------------- scratch (no allocation allowed) ----------------
__device__ __align__(16) float  g_Q[SEQ * ZIPD];          // 4 MB
__device__ __align__(16) float  g_K[SEQ * ZIPD];          // 4 MB
__device__ __align__(16) float  g_T[SEQ * ZIPD];          // 4 MB
__device__ __align__(16) __half g_Kh[SEQ * ZIPD];         // 2 MB  fp16 hi of K-proj
__device__ __align__(16) __half g_Kl[SEQ * ZIPD];         // 2 MB  fp16 lo of K-proj
__device__ __align__(16) __half g_Vt[HEADS * DV * SEQ];   // 8 MB  V transposed per head: [h][n][k]

__device__ __forceinline__ unsigned h2u(__half2 h) { return *reinterpret_cast<unsigned*>(&h); }

// ---------------- fp32 GEMM: C[M,N] = A[M,K] @ W[N,K]^T + bias ----------------
#define BKG 16
#define GPAD 132

// MODE 0: write fp32 C.  MODE 1: write transposed fp16 to g_Vt ([h][n][k] layout).
template <int MODE>
__device__ __forceinline__ void gemm_body(const float* __restrict__ A,
                                          const float* __restrict__ W,
                                          const float* __restrict__ bias,
                                          float* __restrict__ C,
                                          int N, int K)
{
    __shared__ float As[BKG][GPAD];
    __shared__ float Ws[BKG][GPAD];

    const int tid = threadIdx.x;
    const int tx  = tid & 15;
    const int ty  = tid >> 4;
    const int m0  = blockIdx.y * 128;
    const int n0  = blockIdx.x * 128;
    const int lc  = tid & 3;
    const int lr  = tid >> 2;

    float acc[8][8];
#pragma unroll
    for (int i = 0; i < 8; i++)
#pragma unroll
        for (int j = 0; j < 8; j++) acc[i][j] = 0.f;

    for (int k0 = 0; k0 < K; k0 += BKG) {
        float4 a0 = *(const float4*)(A + (size_t)(m0 + lr)      * K + k0 + lc * 4);
        float4 a1 = *(const float4*)(A + (size_t)(m0 + lr + 64) * K + k0 + lc * 4);
        float4 w0 = *(const float4*)(W + (size_t)(n0 + lr)      * K + k0 + lc * 4);
        float4 w1 = *(const float4*)(W + (size_t)(n0 + lr + 64) * K + k0 + lc * 4);

        __syncthreads();
        As[lc * 4 + 0][lr] = a0.x;  As[lc * 4 + 1][lr] = a0.y;
        As[lc * 4 + 2][lr] = a0.z;  As[lc * 4 + 3][lr] = a0.w;
        As[lc * 4 + 0][lr + 64] = a1.x;  As[lc * 4 + 1][lr + 64] = a1.y;
        As[lc * 4 + 2][lr + 64] = a1.z;  As[lc * 4 + 3][lr + 64] = a1.w;
        Ws[lc * 4 + 0][lr] = w0.x;  Ws[lc * 4 + 1][lr] = w0.y;
        Ws[lc * 4 + 2][lr] = w0.z;  Ws[lc * 4 + 3][lr] = w0.w;
        Ws[lc * 4 + 0][lr + 64] = w1.x;  Ws[lc * 4 + 1][lr + 64] = w1.y;
        Ws[lc * 4 + 2][lr + 64] = w1.z;  Ws[lc * 4 + 3][lr + 64] = w1.w;
        __syncthreads();

#pragma unroll
        for (int kk = 0; kk < BKG; kk++) {
            float a[8], b[8];
            float4 t;
            t = *(const float4*)&As[kk][ty * 4];      a[0]=t.x; a[1]=t.y; a[2]=t.z; a[3]=t.w;
            t = *(const float4*)&As[kk][64 + ty * 4]; a[4]=t.x; a[5]=t.y; a[6]=t.z; a[7]=t.w;
            t = *(const float4*)&Ws[kk][tx * 4];      b[0]=t.x; b[1]=t.y; b[2]=t.z; b[3]=t.w;
            t = *(const float4*)&Ws[kk][64 + tx * 4]; b[4]=t.x; b[5]=t.y; b[6]=t.z; b[7]=t.w;
#pragma unroll
            for (int i = 0; i < 8; i++)
#pragma unroll
                for (int j = 0; j < 8; j++)
                    acc[i][j] = fmaf(a[i], b[j], acc[i][j]);
        }
    }

    if (MODE == 0) {
#pragma unroll
        for (int ih = 0; ih < 2; ih++) {
#pragma unroll
            for (int i = 0; i < 4; i++) {
                int row = m0 + ih * 64 + ty * 4 + i;
#pragma unroll
                for (int jh = 0; jh < 2; jh++) {
                    int col = n0 + jh * 64 + tx * 4;
                    float4 o;
                    o.x = acc[ih * 4 + i][jh * 4 + 0] + bias[col + 0];
                    o.y = acc[ih * 4 + i][jh * 4 + 1] + bias[col + 1];
                    o.z = acc[ih * 4 + i][jh * 4 + 2] + bias[col + 2];
                    o.w = acc[ih * 4 + i][jh * 4 + 3] + bias[col + 3];
                    *(float4*)(C + (size_t)row * N + col) = o;
                }
            }
        }
    } else {
        // transposed fp16 epilogue: g_Vt[(h*DV + n)*SEQ + row], rows ty*4..+3 pack into 8B
#pragma unroll
        for (int ih = 0; ih < 2; ih++) {
            int row0 = m0 + ih * 64 + ty * 4;
#pragma unroll
            for (int jh = 0; jh < 2; jh++) {
#pragma unroll
                for (int jj = 0; jj < 4; jj++) {
                    int col = n0 + jh * 64 + tx * 4 + jj;
                    float bv = bias[col];
                    float v0 = acc[ih * 4 + 0][jh * 4 + jj] + bv;
                    float v1 = acc[ih * 4 + 1][jh * 4 + jj] + bv;
                    float v2 = acc[ih * 4 + 2][jh * 4 + jj] + bv;
                    float v3 = acc[ih * 4 + 3][jh * 4 + jj] + bv;
                    __half2 p01 = __floats2half2_rn(v0, v1);
                    __half2 p23 = __floats2half2_rn(v2, v3);
                    int hh = col >> 7;          // head
                    int nn = col & (DV - 1);    // dim within head
                    size_t idx = ((size_t)(hh * DV + nn)) * SEQ + row0;
                    uint2 u; u.x = h2u(p01); u.y = h2u(p23);
                    *reinterpret_cast<uint2*>(&g_Vt[idx]) = u;
                }
            }
        }
    }
}

// z=0 -> Q, z=1 -> K, z=2 -> V right factor
__global__ void __launch_bounds__(256, 2)
proj_kernel(const float* __restrict__ q, const float* __restrict__ k,
            const float* __restrict__ v,
            const float* __restrict__ wq, const float* __restrict__ bq,
            const float* __restrict__ wk, const float* __restrict__ bk,
            const float* __restrict__ wvr, const float* __restrict__ bvr)
{
    const float *A, *W, *B;
    float* C;
    if (blockIdx.z == 0)      { A = q; W = wq;  B = bq;  C = g_Q; }
    else if (blockIdx.z == 1) { A = k; W = wk;  B = bk;  C = g_K; }
    else                      { A = v; W = wvr; B = bvr; C = g_T; }
    gemm_body<0>(A, W, B, C, ZIPD, DMODEL);
}

// value = g_T @ w_v_l^T + b_v_l -> written transposed fp16 into g_Vt
__global__ void __launch_bounds__(256, 2)
vl_kernel(const float* __restrict__ wvl, const float* __restrict__ bvl)
{
    gemm_body<1>(g_T, wvl, bvl, nullptr, DMODEL, ZIPD);
}

// split K projection into fp16 hi + lo (same [key][256] layout)
__global__ void split_k_kernel()
{
    int i = blockIdx.x * 256 + threadIdx.x;   // float4 index; total SEQ*ZIPD/4
    float4 v = ((const float4*)g_K)[i];
    __half h0 = __float2half_rn(v.x), h1 = __float2half_rn(v.y);
    __half h2 = __float2half_rn(v.z), h3 = __float2half_rn(v.w);
    __half2 hi01 = __halves2half2(h0, h1);
    __half2 hi23 = __halves2half2(h2, h3);
    __half2 lo01 = __floats2half2_rn(v.x - __half2float(h0), v.y - __half2float(h1));
    __half2 lo23 = __floats2half2_rn(v.z - __half2float(h2), v.w - __half2float(h3));
    uint2 uh; uh.x = h2u(hi01); uh.y = h2u(hi23);
    uint2 ul; ul.x = h2u(lo01); ul.y = h2u(lo23);
    ((uint2*)g_Kh)[i] = uh;
    ((uint2*)g_Kl)[i] = ul;
}

// ---------------- fp16-MMA flash attention ----------------
__device__ __forceinline__ void mma16816(float& c0, float& c1, float& c2, float& c3,
                                         unsigned a0, unsigned a1, unsigned a2, unsigned a3,
                                         unsigned b0, unsigned b1)
{
    asm volatile("mma.sync.aligned.m16n8k16.row.col.f32.f16.f16.f32 "
                 "{%0,%1,%2,%3},{%4,%5,%6,%7},{%8,%9},{%0,%1,%2,%3};"
                 : "+f"(c0), "+f"(c1), "+f"(c2), "+f"(c3)
                 : "r"(a0), "r"(a1), "r"(a2), "r"(a3), "r"(b0), "r"(b1));
}

#define KSTR 40   // smem K row stride (halves): 32 data + 8 pad -> 20 words == conflict-free
#define VSTR 72   // smem Vt row stride (halves): 64 data + 8 pad -> 36 words == conflict-free

__global__ void __launch_bounds__(128, 2)
attn_kernel(float* __restrict__ O)
{
    __shared__ __align__(16) __half sKh[64 * KSTR];
    __shared__ __align__(16) __half sKl[64 * KSTR];
    __shared__ __align__(16) __half sVt[128 * VSTR];

    const int tid  = threadIdx.x;
    const int wid  = tid >> 5;
    const int lane = tid & 31;
    const int grp  = lane >> 2;
    const int t    = lane & 3;
    const int h    = blockIdx.y;
    const int q0   = blockIdx.x * 64;
    const int qr   = q0 + wid * 16;

    // ---- Q fragments (fp16 hi/lo split), held for the whole kernel ----
    unsigned qh[2][4], ql[2][4];
#pragma unroll
    for (int c = 0; c < 2; c++) {
        int cb = h * DH + 16 * c;
        const float* r0p = g_Q + (size_t)(qr + grp) * ZIPD + cb;
        const float* r1p = g_Q + (size_t)(qr + grp + 8) * ZIPD + cb;
        float2 xs[4];
        xs[0] = *(const float2*)(r0p + 2 * t);        // a0: row grp,   cols 2t,2t+1
        xs[1] = *(const float2*)(r1p + 2 * t);        // a1: row grp+8
        xs[2] = *(const float2*)(r0p + 8 + 2 * t);    // a2: row grp,   cols +8
        xs[3] = *(const float2*)(r1p + 8 + 2 * t);    // a3: row grp+8, cols +8
#pragma unroll
        for (int i = 0; i < 4; i++) {
            __half hx = __float2half_rn(xs[i].x);
            __half hy = __float2half_rn(xs[i].y);
            qh[c][i] = h2u(__halves2half2(hx, hy));
            ql[c][i] = h2u(__floats2half2_rn(xs[i].x - __half2float(hx),
                                             xs[i].y - __half2float(hy)));
        }
    }

    float m0v = -1e30f, m1v = -1e30f, l0 = 0.f, l1 = 0.f;
    float o[16][4];
#pragma unroll
    for (int n = 0; n < 16; n++)
#pragma unroll
        for (int j = 0; j < 4; j++) o[n][j] = 0.f;

    for (int kt = 0; kt < SEQ / 64; kt++) {
        const int k0 = kt * 64;
        __syncthreads();   // previous tile reads done

        // ---- fill K hi/lo tile (straight 16B copies) ----
#pragma unroll
        for (int it = 0; it < 4; it++) {
            int c   = it * 128 + tid;     // 0..511
            int arr = c >> 8;             // 0: hi, 1: lo
            int cc  = c & 255;
            int key = cc >> 2;
            int ch  = cc & 3;
            const __half* src = (arr ? g_Kl : g_Kh) + (size_t)(k0 + key) * ZIPD + h * DH + ch * 8;
            __half* dst = (arr ? sKl : sKh) + key * KSTR + ch * 8;
            *(uint4*)dst = *(const uint4*)src;
        }
        // ---- fill Vt tile: one 64-half row per thread ----
        {
            const __half* src = g_Vt + ((size_t)(h * DV + tid)) * SEQ + k0;
            __half* dst = sVt + tid * VSTR;
#pragma unroll
            for (int j = 0; j < 8; j++)
                *(uint4*)(dst + j * 8) = *(const uint4*)(src + j * 8);
        }
        __syncthreads();

        // ---- S = Q K^T (3-pass fp16 split, fp32 accum) ----
        float sc[8][4];
#pragma unroll
        for (int nb = 0; nb < 8; nb++)
#pragma unroll
            for (int j = 0; j < 4; j++) sc[nb][j] = 0.f;

#pragma unroll
        for (int nb = 0; nb < 8; nb++) {
            const __half* kb  = sKh + (nb * 8 + grp) * KSTR;
            const __half* klp = sKl + (nb * 8 + grp) * KSTR;
#pragma unroll
            for (int c = 0; c < 2; c++) {
                unsigned bh0 = *(const unsigned*)(kb  + 16 * c + 2 * t);
                unsigned bh1 = *(const unsigned*)(kb  + 16 * c + 8 + 2 * t);
                unsigned bl0 = *(const unsigned*)(klp + 16 * c + 2 * t);
                unsigned bl1 = *(const unsigned*)(klp + 16 * c + 8 + 2 * t);
                mma16816(sc[nb][0], sc[nb][1], sc[nb][2], sc[nb][3],
                         qh[c][0], qh[c][1], qh[c][2], qh[c][3], bh0, bh1);
                mma16816(sc[nb][0], sc[nb][1], sc[nb][2], sc[nb][3],
                         qh[c][0], qh[c][1], qh[c][2], qh[c][3], bl0, bl1);
                mma16816(sc[nb][0], sc[nb][1], sc[nb][2], sc[nb][3],
                         ql[c][0], ql[c][1], ql[c][2], ql[c][3], bh0, bh1);
            }
        }

        // ---- online softmax: thread owns rows grp (regs 0,1) and grp+8 (regs 2,3) ----
        float mx0 = -1e30f, mx1 = -1e30f;
#pragma unroll
        for (int nb = 0; nb < 8; nb++) {
            mx0 = fmaxf(mx0, fmaxf(sc[nb][0], sc[nb][1]));
            mx1 = fmaxf(mx1, fmaxf(sc[nb][2], sc[nb][3]));
        }
        mx0 = fmaxf(mx0, __shfl_xor_sync(0xffffffffu, mx0, 1));
        mx0 = fmaxf(mx0, __shfl_xor_sync(0xffffffffu, mx0, 2));
        mx1 = fmaxf(mx1, __shfl_xor_sync(0xffffffffu, mx1, 1));
        mx1 = fmaxf(mx1, __shfl_xor_sync(0xffffffffu, mx1, 2));

        float mn0 = fmaxf(m0v, mx0), mn1 = fmaxf(m1v, mx1);
        float e0 = __expf(m0v - mn0), e1 = __expf(m1v - mn1);
        m0v = mn0; m1v = mn1;

        float s0 = 0.f, s1 = 0.f;
#pragma unroll
        for (int nb = 0; nb < 8; nb++) {
            sc[nb][0] = __expf(sc[nb][0] - mn0);
            sc[nb][1] = __expf(sc[nb][1] - mn0);
            sc[nb][2] = __expf(sc[nb][2] - mn1);
            sc[nb][3] = __expf(sc[nb][3] - mn1);
            s0 += sc[nb][0] + sc[nb][1];
            s1 += sc[nb][2] + sc[nb][3];
        }
        s0 += __shfl_xor_sync(0xffffffffu, s0, 1);
        s0 += __shfl_xor_sync(0xffffffffu, s0, 2);
        s1 += __shfl_xor_sync(0xffffffffu, s1, 1);
        s1 += __shfl_xor_sync(0xffffffffu, s1, 2);
        l0 = l0 * e0 + s0;
        l1 = l1 * e1 + s1;

#pragma unroll
        for (int n = 0; n < 16; n++) {
            o[n][0] *= e0; o[n][1] *= e0;
            o[n][2] *= e1; o[n][3] *= e1;
        }

        // ---- O += P V : P packs directly from C-frags into A-frags ----
#pragma unroll
        for (int j = 0; j < 4; j++) {
            unsigned a0 = h2u(__floats2half2_rn(sc[2 * j][0],     sc[2 * j][1]));
            unsigned a1 = h2u(__floats2half2_rn(sc[2 * j][2],     sc[2 * j][3]));
            unsigned a2 = h2u(__floats2half2_rn(sc[2 * j + 1][0], sc[2 * j + 1][1]));
            unsigned a3 = h2u(__floats2half2_rn(sc[2 * j + 1][2], sc[2 * j + 1][3]));
#pragma unroll
            for (int nb2 = 0; nb2 < 16; nb2++) {
                const __half* vb = sVt + (nb2 * 8 + grp) * VSTR + j * 16;
                unsigned b0 = *(const unsigned*)(vb + 2 * t);
                unsigned b1 = *(const unsigned*)(vb + 8 + 2 * t);
                mma16816(o[nb2][0], o[nb2][1], o[nb2][2], o[nb2][3], a0, a1, a2, a3, b0, b1);
            }
        }
    }

    // ---- epilogue ----
    float inv0 = 1.f / l0, inv1 = 1.f / l1;
    int row0 = qr + grp, row1 = qr + grp + 8;
#pragma unroll
    for (int nb2 = 0; nb2 < 16; nb2++) {
        int col = h * DV + nb2 * 8 + 2 * t;
        *(float2*)(O + (size_t)row0 * DMODEL + col) = make_float2(o[nb2][0] * inv0, o[nb2][1] * inv0);
        *(float2*)(O + (size_t)row1 * DMODEL + col) = make_float2(o[nb2][2] * inv1, o[nb2][3] * inv1);
    }
}

// ---------------- launch ----------------
extern "C" void kernel_launch(void* const* d_in, const int* in_sizes, int n_in,
                              void* d_out, int out_size)
{
    const float* q   = (const float*)d_in[0];
    const float* k   = (const float*)d_in[1];
    const float* v   = (const float*)d_in[2];
    const float* wq  = (const float*)d_in[3];
    const float* bq  = (const float*)d_in[4];
    const float* wk  = (const float*)d_in[5];
    const float* bk  = (const float*)d_in[6];
    const float* wvr = (const float*)d_in[7];
    const float* bvr = (const float*)d_in[8];
    const float* wvl = (const float*)d_in[9];
    const float* bvl = (const float*)d_in[10];
    float* out = (float*)d_out;

    dim3 pgrid(ZIPD / 128, SEQ / 128, 3);
    proj_kernel<<<pgrid, 256>>>(q, k, v, wq, bq, wk, bk, wvr, bvr);

    split_k_kernel<<<(SEQ * ZIPD / 4) / 256, 256>>>();

    dim3 vgrid(DMODEL / 128, SEQ / 128, 1);
    vl_kernel<<<vgrid, 256>>>(wvl, bvl);

    attn_kernel<<<dim3(SEQ / 64, HEADS), 128>>>(out);
}